// round 15
// baseline (speedup 1.0000x reference)
#include <cuda_runtime.h>
#include <stdint.h>

// Problem constants (fixed by setup_inputs)
#define BB 512        // batch rows
#define NN 100000     // reference points
#define DD 10         // logit dim
#define CC 3072       // x feature dim
#define KNN 50
#define RROWS 8       // rows per CTA tile in main pass (halves L2 traffic)
#define RGRP (BB / RROWS)   // 64
#define JCH 23        // 64*23 = 1472 CTAs ~= 5 waves of 296 (occ 2)
#define CAP 8192      // global candidate buffer per row
#define CCAP 128      // per-CTA smem staging per row (exp ~17, huge margin)
#define TPB 256
#define TROWS 2       // rows per CTA in threshold kernel (32KB smem key cache)
#define TSAMP 4096    // sample size (first TSAMP points)
#define TMSEL 16      // threshold = TMSEL-th smallest sample key (E[cand]~390)
#define TIECAP 512
#define PREP_BLOCKS ((NN + TPB - 1) / TPB)   // 391
#define LOGITS_BLOCKS (BB / 8)               // 64 (8 warps per block)

// Scratch (static device globals — allocation-free)
// SoA float4 planes: A = x0..x3, B = x4..x7, C = (x8, x9, xsq, yf).
__device__ float4             g_XA[NN];
__device__ float4             g_XB[NN];
__device__ float4             g_XC[NN];
__device__ float              g_L[BB * DD];
__device__ float              g_scale[BB];
__device__ float              g_T[BB];
__device__ int                g_ccount[BB];
__device__ unsigned long long g_cand[(size_t)BB * CAP]; // 32 MB

// Order-preserving float -> uint map and inverse
__device__ __forceinline__ unsigned mono(float f) {
    unsigned u = __float_as_uint(f);
    return u ^ ((unsigned)((int)u >> 31) | 0x80000000u);
}
__device__ __forceinline__ float unmono(unsigned v) {
    unsigned u = (v & 0x80000000u) ? (v ^ 0x80000000u) : ~v;
    return __uint_as_float(u);
}

// Key: xsq - 2*dot(L,x), fixed fmaf order — SAME chain in every kernel,
// so keys are bitwise identical everywhere.
__device__ __forceinline__ float keyval(const float* L, const float* xv, float xsq) {
    float acc = 0.f;
#pragma unroll
    for (int c = 0; c < DD; c++) acc = fmaf(L[c], xv[c], acc);
    return fmaf(-2.f, acc, xsq);
}

// Parallel 256-bin select: find bin b s.t. prefix(b) < remaining <= prefix(b+1).
__device__ __forceinline__ void binselect256(unsigned* hist, unsigned* scanbuf,
                                             int remaining, unsigned* sel, unsigned* run) {
    int tid = threadIdx.x;
    unsigned cnt = (tid < 256) ? hist[tid] : 0u;
    scanbuf[tid] = cnt;
    __syncthreads();
#pragma unroll
    for (int off = 1; off < 256; off <<= 1) {
        unsigned v = (tid >= off && tid < 256) ? scanbuf[tid - off] : 0u;
        __syncthreads();
        if (tid < 256) scanbuf[tid] += v;
        __syncthreads();
    }
    if (tid < 256) {
        unsigned incl = scanbuf[tid];
        unsigned excl = incl - cnt;
        if (excl < (unsigned)remaining && incl >= (unsigned)remaining) {
            *sel = (unsigned)tid;
            *run = excl;
        }
    }
    __syncthreads();
}

// ---------------------------------------------------------------------------
// Kernel 0 (fused): blocks [0,PREP_BLOCKS) pack X into SoA (smem-staged,
// coalesced); blocks [PREP_BLOCKS, +LOGITS_BLOCKS) compute logits (float2 W).
// ---------------------------------------------------------------------------
__global__ void k_setup(const float* __restrict__ X, const int* __restrict__ Y,
                        const float* __restrict__ x, const float* __restrict__ W,
                        const float* __restrict__ bias, float* __restrict__ out) {
    int tid = threadIdx.x;
    if (blockIdx.x < PREP_BLOCKS) {
        __shared__ float sX[TPB * DD];   // 10 KB
        int base = blockIdx.x * TPB;
        int nrow = min(TPB, NN - base);
        int nflt = nrow * DD;
        // coalesced global -> smem (1 line per warp-load)
        for (int t = tid; t < nflt; t += TPB) sX[t] = X[(size_t)base * DD + t];
        __syncthreads();
        int i = base + tid;
        if (i < BB) g_ccount[i] = 0;
        if (tid < nrow) {
            float v[DD];
            float xsq = 0.f;
#pragma unroll
            for (int c = 0; c < DD; c++) { v[c] = sX[tid * DD + c]; xsq = fmaf(v[c], v[c], xsq); }
            g_XA[i] = make_float4(v[0], v[1], v[2], v[3]);
            g_XB[i] = make_float4(v[4], v[5], v[6], v[7]);
            g_XC[i] = make_float4(v[8], v[9], xsq, (float)(2 * Y[i] - 1));
        }
    } else {
        int warp = tid >> 5, lane = tid & 31;
        int row = (blockIdx.x - PREP_BLOCKS) * 8 + warp;
        const float* xr = x + (size_t)row * CC;
        float acc[DD];
#pragma unroll
        for (int c = 0; c < DD; c++) acc[c] = 0.f;
        for (int k = lane; k < CC; k += 32) {
            float xv = xr[k];
            const float2* wr = (const float2*)(W + (size_t)k * DD);  // 8B-aligned (40B rows)
            float2 w0 = wr[0], w1 = wr[1], w2 = wr[2], w3 = wr[3], w4 = wr[4];
            acc[0] = fmaf(xv, w0.x, acc[0]); acc[1] = fmaf(xv, w0.y, acc[1]);
            acc[2] = fmaf(xv, w1.x, acc[2]); acc[3] = fmaf(xv, w1.y, acc[3]);
            acc[4] = fmaf(xv, w2.x, acc[4]); acc[5] = fmaf(xv, w2.y, acc[5]);
            acc[6] = fmaf(xv, w3.x, acc[6]); acc[7] = fmaf(xv, w3.y, acc[7]);
            acc[8] = fmaf(xv, w4.x, acc[8]); acc[9] = fmaf(xv, w4.y, acc[9]);
        }
#pragma unroll
        for (int c = 0; c < DD; c++)
#pragma unroll
            for (int off = 16; off > 0; off >>= 1)
                acc[c] += __shfl_down_sync(0xFFFFFFFFu, acc[c], off);
        if (lane == 0) {
            float mx = 0.f;
#pragma unroll
            for (int c = 0; c < DD; c++) {
                float l = acc[c] + bias[c];
                g_L[row * DD + c] = l;
                out[row * 11 + c] = l;
                mx = fmaxf(mx, fabsf(l));
            }
            g_scale[row] = 2.f * mx;
        }
    }
}

// ---------------------------------------------------------------------------
// Kernel 1: threshold — 2 rows/CTA, sample keys computed ONCE into smem
//           (32 KB), per-row exact radix-select of TMSEL-th -> g_T[row]
// ---------------------------------------------------------------------------
__global__ void k_thresh2() {
    __shared__ unsigned skey[TROWS][TSAMP];   // 32 KB
    __shared__ unsigned hist[256];
    __shared__ unsigned scanbuf[TPB];
    __shared__ unsigned s_sel, s_run;
    int tid = threadIdx.x;
    int row0 = blockIdx.x * TROWS;
    float L[TROWS][DD];
#pragma unroll
    for (int r = 0; r < TROWS; r++)
#pragma unroll
        for (int c = 0; c < DD; c++) L[r][c] = g_L[(row0 + r) * DD + c];
    for (int s = tid; s < TSAMP; s += TPB) {
        float4 a = g_XA[s], b = g_XB[s], c4 = g_XC[s];
        float xv[DD] = {a.x, a.y, a.z, a.w, b.x, b.y, b.z, b.w, c4.x, c4.y};
#pragma unroll
        for (int r = 0; r < TROWS; r++) skey[r][s] = mono(keyval(L[r], xv, c4.z));
    }
    __syncthreads();
    for (int r = 0; r < TROWS; r++) {
        unsigned prefix = 0;
        int remaining = TMSEL;
        for (int pass = 0; pass < 4; pass++) {
            int shift = 24 - 8 * pass;
            unsigned maskhi = pass ? (0xFFFFFFFFu << (32 - 8 * pass)) : 0u;
            if (tid < 256) hist[tid] = 0u;
            __syncthreads();
            for (int i = tid; i < TSAMP; i += TPB) {
                unsigned u = skey[r][i];
                if ((u & maskhi) == prefix) atomicAdd(&hist[(u >> shift) & 255], 1u);
            }
            __syncthreads();
            binselect256(hist, scanbuf, remaining, &s_sel, &s_run);
            remaining -= (int)s_run;
            prefix |= s_sel << shift;
            __syncthreads();
        }
        if (tid == 0) g_T[row0 + r] = unmono(prefix);
        __syncthreads();
    }
}

// ---------------------------------------------------------------------------
// Kernel 2: main pass — scalar FFMA, 8 rows/CTA, 2 CTAs/SM (16 warps),
//           smem candidate staging. Halves L2 traffic vs RROWS=4 (307 MB).
// ---------------------------------------------------------------------------
__global__ void __launch_bounds__(TPB, 2) k_main() {
    __shared__ unsigned long long sbuf[RROWS][CCAP];   // 8 KB
    __shared__ int scnt[RROWS];
    __shared__ int sbase[RROWS];
    int tid = threadIdx.x;
    int row0 = blockIdx.x * RROWS;
    if (tid < RROWS) scnt[tid] = 0;
    float L[RROWS][DD];
    float Tf[RROWS];
#pragma unroll
    for (int r = 0; r < RROWS; r++) {
        Tf[r] = g_T[row0 + r];
#pragma unroll
        for (int c = 0; c < DD; c++) L[r][c] = g_L[(row0 + r) * DD + c];
    }
    __syncthreads();

    const int chunk = (NN + JCH - 1) / JCH;
    int jbeg = blockIdx.y * chunk;
    int jend = min(NN, jbeg + chunk);

    for (int j = jbeg + tid; j < jend; j += TPB) {
        float4 a = g_XA[j], b = g_XB[j], c4 = g_XC[j];
        float xv[DD] = {a.x, a.y, a.z, a.w, b.x, b.y, b.z, b.w, c4.x, c4.y};
#pragma unroll
        for (int r = 0; r < RROWS; r++) {
            float k = keyval(L[r], xv, c4.z);
            if (k <= Tf[r]) {
                int slot = atomicAdd(&scnt[r], 1);      // smem atomic: ~35 cyc
                if (slot < CCAP)
                    sbuf[r][slot] = ((unsigned long long)mono(k) << 32) | (unsigned)j;
            }
        }
    }
    __syncthreads();

    // Flush staged candidates: one global atomic per row, coalesced stores.
    if (tid < RROWS) {
        int r = tid;
        int n = scnt[r];
        // overflow (never expected): force ccount > CAP so k_final's fallback recomputes
        int add = (n > CCAP) ? (CAP + 1) : n;
        sbase[r] = atomicAdd(&g_ccount[row0 + r], add);
    }
    __syncthreads();
#pragma unroll
    for (int r = 0; r < RROWS; r++) {
        int n = min(scnt[r], CCAP);
        int base = sbase[r];
        for (int i = tid; i < n; i += TPB) {
            int slot = base + i;
            if (slot < CAP) g_cand[(size_t)(row0 + r) * CAP + slot] = sbuf[r][i];
        }
    }
}

// ---------------------------------------------------------------------------
// Kernel 3: per-row select + vote + adversarial logit. Includes inline exact
//           bisection fallback when the candidate set is bad (never expected).
// ---------------------------------------------------------------------------
__global__ void k_final(float* __restrict__ out) {
    int row = blockIdx.x, tid = threadIdx.x;
    int c = g_ccount[row];
    unsigned long long* cd = &g_cand[(size_t)row * CAP];
    __shared__ unsigned hist[256];
    __shared__ unsigned scanbuf[TPB];
    __shared__ unsigned s_sel, s_run;
    __shared__ int s_refill;

    if (c < KNN || c > CAP) {
        // Exact bisection on mono keys over all N points, then refill g_cand.
        float L[DD];
#pragma unroll
        for (int i = 0; i < DD; i++) L[i] = g_L[row * DD + i];
        __shared__ int scnt2[TPB];
        unsigned lo = 0u, hi = 0xFFFFFFFFu;
        for (int it = 0; it < 32 && lo < hi; it++) {
            unsigned mid = lo + ((hi - lo) >> 1);
            int cnt = 0;
            for (int j = tid; j < NN; j += TPB) {
                float4 a = g_XA[j], b = g_XB[j], c4 = g_XC[j];
                float xv[DD] = {a.x, a.y, a.z, a.w, b.x, b.y, b.z, b.w, c4.x, c4.y};
                cnt += (mono(keyval(L, xv, c4.z)) <= mid);
            }
            scnt2[tid] = cnt;
            __syncthreads();
            for (int st = TPB / 2; st > 0; st >>= 1) {
                if (tid < st) scnt2[tid] += scnt2[tid + st];
                __syncthreads();
            }
            int tot = scnt2[0];
            __syncthreads();
            if (tot >= KNN) hi = mid; else lo = mid + 1;
        }
        if (tid == 0) s_refill = 0;
        __syncthreads();
        for (int j = tid; j < NN; j += TPB) {
            float4 a = g_XA[j], b = g_XB[j], c4 = g_XC[j];
            float xv[DD] = {a.x, a.y, a.z, a.w, b.x, b.y, b.z, b.w, c4.x, c4.y};
            unsigned u = mono(keyval(L, xv, c4.z));
            if (u <= lo) {
                int slot = atomicAdd(&s_refill, 1);
                if (slot < CAP) cd[slot] = ((unsigned long long)u << 32) | (unsigned)j;
            }
        }
        __syncthreads();
        c = min(s_refill, CAP);
    }
    c = min(c, CAP);

    // Exact radix-select of the KNN-th smallest key among candidates.
    unsigned prefix = 0;
    int remaining = KNN;
    for (int pass = 0; pass < 4; pass++) {
        int shift = 24 - 8 * pass;
        unsigned maskhi = pass ? (0xFFFFFFFFu << (32 - 8 * pass)) : 0u;
        if (tid < 256) hist[tid] = 0u;
        __syncthreads();
        for (int i = tid; i < c; i += TPB) {
            unsigned u = (unsigned)(cd[i] >> 32);
            if ((u & maskhi) == prefix) atomicAdd(&hist[(u >> shift) & 255], 1u);
        }
        __syncthreads();
        binselect256(hist, scanbuf, remaining, &s_sel, &s_run);
        remaining -= (int)s_run;
        prefix |= s_sel << shift;
        __syncthreads();
    }
    unsigned k50 = prefix;
    int t = remaining;  // take t smallest-index elements among key==k50 ties

    __shared__ int s_tn;
    __shared__ unsigned tiebuf[TIECAP];
    if (tid == 0) s_tn = 0;
    __syncthreads();
    float local = 0.f;
    for (int i = tid; i < c; i += TPB) {
        unsigned long long v = cd[i];
        unsigned u = (unsigned)(v >> 32);
        unsigned j = (unsigned)(v & 0xFFFFFFFFu);
        if (u < k50) {
            local += g_XC[j].w;  // yf
        } else if (u == k50) {
            int p = atomicAdd(&s_tn, 1);
            if (p < TIECAP) tiebuf[p] = j;
        }
    }
    __syncthreads();
    int nt = min(s_tn, TIECAP);
    for (int i = tid; i < nt; i += TPB) {
        unsigned ji = tiebuf[i];
        int rank = 0;
        for (int k = 0; k < nt; k++) rank += (tiebuf[k] < ji);
        if (rank < t) local += g_XC[ji].w;
    }
    __shared__ float sv[TPB];
    sv[tid] = local;
    __syncthreads();
    for (int st = TPB / 2; st > 0; st >>= 1) {
        if (tid < st) sv[tid] += sv[tid + st];
        __syncthreads();
    }
    if (tid == 0) {
        float v = sv[0];  // + BIAS (= 0)
        float sgn = (v > 0.f) ? 1.f : ((v < 0.f) ? -1.f : 0.f);
        out[row * 11 + 10] = sgn * g_scale[row];
    }
}

// ---------------------------------------------------------------------------
extern "C" void kernel_launch(void* const* d_in, const int* in_sizes, int n_in,
                              void* d_out, int out_size) {
    const float* x    = (const float*)d_in[0];
    const float* W    = (const float*)d_in[1];
    const float* bias = (const float*)d_in[2];
    const float* X    = (const float*)d_in[3];
    const int*   Y    = (const int*)d_in[4];
    float* out = (float*)d_out;

    k_setup<<<PREP_BLOCKS + LOGITS_BLOCKS, TPB>>>(X, Y, x, W, bias, out);
    k_thresh2<<<BB / TROWS, TPB>>>();
    k_main<<<dim3(RGRP, JCH), TPB>>>();
    k_final<<<BB, TPB>>>(out);
}

// round 17
// speedup vs baseline: 1.0559x; 1.0559x over previous
#include <cuda_runtime.h>
#include <stdint.h>

// Problem constants (fixed by setup_inputs)
#define BB 512        // batch rows
#define NN 100000     // reference points
#define DD 10         // logit dim
#define CC 3072       // x feature dim
#define KNN 50
#define RROWS 4       // rows per CTA tile in main pass (low regs -> 4 CTAs/SM)
#define RGRP (BB / RROWS)   // 128
#define JCH 18        // j-chunks: 128*18 = 2304 CTAs (4 waves of 592 @ occ 4)
#define CAP 8192      // global candidate buffer per row
#define CCAP 256      // per-CTA smem candidate staging per row (exp ~22)
#define TPB 256
#define TROWS 2       // rows per CTA in threshold kernel (32KB smem key cache)
#define TSAMP 4096    // sample size (first TSAMP points)
#define TMSEL 16      // threshold = TMSEL-th smallest sample key (E[cand]~390)
#define TIECAP 512
#define PREP_BLOCKS ((NN + TPB - 1) / TPB)   // 391
#define LOGITS_BLOCKS (BB / 8)               // 64 (8 warps per block)

// Scratch (static device globals — allocation-free)
// SoA float4 planes: A = x0..x3, B = x4..x7, C = (x8, x9, xsq, yf).
__device__ float4             g_XA[NN];
__device__ float4             g_XB[NN];
__device__ float4             g_XC[NN];
__device__ float              g_L[BB * DD];
__device__ float              g_scale[BB];
__device__ float              g_T[BB];
__device__ int                g_ccount[BB];
__device__ unsigned long long g_cand[(size_t)BB * CAP]; // 32 MB

// Order-preserving float -> uint map and inverse
__device__ __forceinline__ unsigned mono(float f) {
    unsigned u = __float_as_uint(f);
    return u ^ ((unsigned)((int)u >> 31) | 0x80000000u);
}
__device__ __forceinline__ float unmono(unsigned v) {
    unsigned u = (v & 0x80000000u) ? (v ^ 0x80000000u) : ~v;
    return __uint_as_float(u);
}

// Key: xsq - 2*dot(L,x), fixed fmaf order — SAME chain in every kernel,
// so keys are bitwise identical everywhere.
__device__ __forceinline__ float keyval(const float* L, const float* xv, float xsq) {
    float acc = 0.f;
#pragma unroll
    for (int c = 0; c < DD; c++) acc = fmaf(L[c], xv[c], acc);
    return fmaf(-2.f, acc, xsq);
}

// Parallel 256-bin select: find bin b s.t. prefix(b) < remaining <= prefix(b+1).
__device__ __forceinline__ void binselect256(unsigned* hist, unsigned* scanbuf,
                                             int remaining, unsigned* sel, unsigned* run) {
    int tid = threadIdx.x;
    unsigned cnt = (tid < 256) ? hist[tid] : 0u;
    scanbuf[tid] = cnt;
    __syncthreads();
#pragma unroll
    for (int off = 1; off < 256; off <<= 1) {
        unsigned v = (tid >= off && tid < 256) ? scanbuf[tid - off] : 0u;
        __syncthreads();
        if (tid < 256) scanbuf[tid] += v;
        __syncthreads();
    }
    if (tid < 256) {
        unsigned incl = scanbuf[tid];
        unsigned excl = incl - cnt;
        if (excl < (unsigned)remaining && incl >= (unsigned)remaining) {
            *sel = (unsigned)tid;
            *run = excl;
        }
    }
    __syncthreads();
}

// ---------------------------------------------------------------------------
// Kernel 0 (fused): blocks [0,PREP_BLOCKS) pack X into SoA (smem-staged,
// coalesced); blocks [PREP_BLOCKS, +LOGITS_BLOCKS) compute logits (float2 W).
// ---------------------------------------------------------------------------
__global__ void k_setup(const float* __restrict__ X, const int* __restrict__ Y,
                        const float* __restrict__ x, const float* __restrict__ W,
                        const float* __restrict__ bias, float* __restrict__ out) {
    int tid = threadIdx.x;
    if (blockIdx.x < PREP_BLOCKS) {
        __shared__ float sX[TPB * DD];   // 10 KB
        int base = blockIdx.x * TPB;
        int nrow = min(TPB, NN - base);
        int nflt = nrow * DD;
        // coalesced global -> smem (1 line per warp-load)
        for (int t = tid; t < nflt; t += TPB) sX[t] = X[(size_t)base * DD + t];
        __syncthreads();
        int i = base + tid;
        if (i < BB) g_ccount[i] = 0;
        if (tid < nrow) {
            float v[DD];
            float xsq = 0.f;
#pragma unroll
            for (int c = 0; c < DD; c++) { v[c] = sX[tid * DD + c]; xsq = fmaf(v[c], v[c], xsq); }
            g_XA[i] = make_float4(v[0], v[1], v[2], v[3]);
            g_XB[i] = make_float4(v[4], v[5], v[6], v[7]);
            g_XC[i] = make_float4(v[8], v[9], xsq, (float)(2 * Y[i] - 1));
        }
    } else {
        int warp = tid >> 5, lane = tid & 31;
        int row = (blockIdx.x - PREP_BLOCKS) * 8 + warp;
        const float* xr = x + (size_t)row * CC;
        float acc[DD];
#pragma unroll
        for (int c = 0; c < DD; c++) acc[c] = 0.f;
        for (int k = lane; k < CC; k += 32) {
            float xv = xr[k];
            const float2* wr = (const float2*)(W + (size_t)k * DD);  // 8B-aligned (40B rows)
            float2 w0 = wr[0], w1 = wr[1], w2 = wr[2], w3 = wr[3], w4 = wr[4];
            acc[0] = fmaf(xv, w0.x, acc[0]); acc[1] = fmaf(xv, w0.y, acc[1]);
            acc[2] = fmaf(xv, w1.x, acc[2]); acc[3] = fmaf(xv, w1.y, acc[3]);
            acc[4] = fmaf(xv, w2.x, acc[4]); acc[5] = fmaf(xv, w2.y, acc[5]);
            acc[6] = fmaf(xv, w3.x, acc[6]); acc[7] = fmaf(xv, w3.y, acc[7]);
            acc[8] = fmaf(xv, w4.x, acc[8]); acc[9] = fmaf(xv, w4.y, acc[9]);
        }
#pragma unroll
        for (int c = 0; c < DD; c++)
#pragma unroll
            for (int off = 16; off > 0; off >>= 1)
                acc[c] += __shfl_down_sync(0xFFFFFFFFu, acc[c], off);
        if (lane == 0) {
            float mx = 0.f;
#pragma unroll
            for (int c = 0; c < DD; c++) {
                float l = acc[c] + bias[c];
                g_L[row * DD + c] = l;
                out[row * 11 + c] = l;
                mx = fmaxf(mx, fabsf(l));
            }
            g_scale[row] = 2.f * mx;
        }
    }
}

// ---------------------------------------------------------------------------
// Kernel 1: threshold — 2 rows/CTA, sample keys computed ONCE into smem
//           (32 KB), per-row exact radix-select of TMSEL-th -> g_T[row]
// ---------------------------------------------------------------------------
__global__ void k_thresh2() {
    __shared__ unsigned skey[TROWS][TSAMP];   // 32 KB
    __shared__ unsigned hist[256];
    __shared__ unsigned scanbuf[TPB];
    __shared__ unsigned s_sel, s_run;
    int tid = threadIdx.x;
    int row0 = blockIdx.x * TROWS;
    float L[TROWS][DD];
#pragma unroll
    for (int r = 0; r < TROWS; r++)
#pragma unroll
        for (int c = 0; c < DD; c++) L[r][c] = g_L[(row0 + r) * DD + c];
    for (int s = tid; s < TSAMP; s += TPB) {
        float4 a = g_XA[s], b = g_XB[s], c4 = g_XC[s];
        float xv[DD] = {a.x, a.y, a.z, a.w, b.x, b.y, b.z, b.w, c4.x, c4.y};
#pragma unroll
        for (int r = 0; r < TROWS; r++) skey[r][s] = mono(keyval(L[r], xv, c4.z));
    }
    __syncthreads();
    for (int r = 0; r < TROWS; r++) {
        unsigned prefix = 0;
        int remaining = TMSEL;
        for (int pass = 0; pass < 4; pass++) {
            int shift = 24 - 8 * pass;
            unsigned maskhi = pass ? (0xFFFFFFFFu << (32 - 8 * pass)) : 0u;
            if (tid < 256) hist[tid] = 0u;
            __syncthreads();
            for (int i = tid; i < TSAMP; i += TPB) {
                unsigned u = skey[r][i];
                if ((u & maskhi) == prefix) atomicAdd(&hist[(u >> shift) & 255], 1u);
            }
            __syncthreads();
            binselect256(hist, scanbuf, remaining, &s_sel, &s_run);
            remaining -= (int)s_run;
            prefix |= s_sel << shift;
            __syncthreads();
        }
        if (tid == 0) g_T[row0 + r] = unmono(prefix);
        __syncthreads();
    }
}

// ---------------------------------------------------------------------------
// Kernel 2: main pass — scalar FFMA, 4 rows/CTA, 4 CTAs/SM (32 warps),
//           smem candidate staging (R10/R14-proven config)
// ---------------------------------------------------------------------------
__global__ void __launch_bounds__(TPB, 4) k_main() {
    __shared__ unsigned long long sbuf[RROWS][CCAP];   // 8 KB
    __shared__ int scnt[RROWS];
    __shared__ int sbase[RROWS];
    int tid = threadIdx.x;
    int row0 = blockIdx.x * RROWS;
    if (tid < RROWS) scnt[tid] = 0;
    float L[RROWS][DD];
    float Tf[RROWS];
#pragma unroll
    for (int r = 0; r < RROWS; r++) {
        Tf[r] = g_T[row0 + r];
#pragma unroll
        for (int c = 0; c < DD; c++) L[r][c] = g_L[(row0 + r) * DD + c];
    }
    __syncthreads();

    const int chunk = (NN + JCH - 1) / JCH;
    int jbeg = blockIdx.y * chunk;
    int jend = min(NN, jbeg + chunk);

    for (int j = jbeg + tid; j < jend; j += TPB) {
        float4 a = g_XA[j], b = g_XB[j], c4 = g_XC[j];
        float xv[DD] = {a.x, a.y, a.z, a.w, b.x, b.y, b.z, b.w, c4.x, c4.y};
#pragma unroll
        for (int r = 0; r < RROWS; r++) {
            float k = keyval(L[r], xv, c4.z);
            if (k <= Tf[r]) {
                int slot = atomicAdd(&scnt[r], 1);      // smem atomic: ~35 cyc
                if (slot < CCAP)
                    sbuf[r][slot] = ((unsigned long long)mono(k) << 32) | (unsigned)j;
            }
        }
    }
    __syncthreads();

    // Flush staged candidates: one global atomic per row, coalesced stores.
    if (tid < RROWS) {
        int r = tid;
        int n = scnt[r];
        // overflow (never expected): force ccount > CAP so k_final's fallback recomputes
        int add = (n > CCAP) ? (CAP + 1) : n;
        sbase[r] = atomicAdd(&g_ccount[row0 + r], add);
    }
    __syncthreads();
#pragma unroll
    for (int r = 0; r < RROWS; r++) {
        int n = min(scnt[r], CCAP);
        int base = sbase[r];
        for (int i = tid; i < n; i += TPB) {
            int slot = base + i;
            if (slot < CAP) g_cand[(size_t)(row0 + r) * CAP + slot] = sbuf[r][i];
        }
    }
}

// ---------------------------------------------------------------------------
// Kernel 3: per-row select + vote + adversarial logit. Includes inline exact
//           bisection fallback when the candidate set is bad (never expected).
// ---------------------------------------------------------------------------
__global__ void k_final(float* __restrict__ out) {
    int row = blockIdx.x, tid = threadIdx.x;
    int c = g_ccount[row];
    unsigned long long* cd = &g_cand[(size_t)row * CAP];
    __shared__ unsigned hist[256];
    __shared__ unsigned scanbuf[TPB];
    __shared__ unsigned s_sel, s_run;
    __shared__ int s_refill;

    if (c < KNN || c > CAP) {
        // Exact bisection on mono keys over all N points, then refill g_cand.
        float L[DD];
#pragma unroll
        for (int i = 0; i < DD; i++) L[i] = g_L[row * DD + i];
        __shared__ int scnt2[TPB];
        unsigned lo = 0u, hi = 0xFFFFFFFFu;
        for (int it = 0; it < 32 && lo < hi; it++) {
            unsigned mid = lo + ((hi - lo) >> 1);
            int cnt = 0;
            for (int j = tid; j < NN; j += TPB) {
                float4 a = g_XA[j], b = g_XB[j], c4 = g_XC[j];
                float xv[DD] = {a.x, a.y, a.z, a.w, b.x, b.y, b.z, b.w, c4.x, c4.y};
                cnt += (mono(keyval(L, xv, c4.z)) <= mid);
            }
            scnt2[tid] = cnt;
            __syncthreads();
            for (int st = TPB / 2; st > 0; st >>= 1) {
                if (tid < st) scnt2[tid] += scnt2[tid + st];
                __syncthreads();
            }
            int tot = scnt2[0];
            __syncthreads();
            if (tot >= KNN) hi = mid; else lo = mid + 1;
        }
        if (tid == 0) s_refill = 0;
        __syncthreads();
        for (int j = tid; j < NN; j += TPB) {
            float4 a = g_XA[j], b = g_XB[j], c4 = g_XC[j];
            float xv[DD] = {a.x, a.y, a.z, a.w, b.x, b.y, b.z, b.w, c4.x, c4.y};
            unsigned u = mono(keyval(L, xv, c4.z));
            if (u <= lo) {
                int slot = atomicAdd(&s_refill, 1);
                if (slot < CAP) cd[slot] = ((unsigned long long)u << 32) | (unsigned)j;
            }
        }
        __syncthreads();
        c = min(s_refill, CAP);
    }
    c = min(c, CAP);

    // Exact radix-select of the KNN-th smallest key among candidates.
    unsigned prefix = 0;
    int remaining = KNN;
    for (int pass = 0; pass < 4; pass++) {
        int shift = 24 - 8 * pass;
        unsigned maskhi = pass ? (0xFFFFFFFFu << (32 - 8 * pass)) : 0u;
        if (tid < 256) hist[tid] = 0u;
        __syncthreads();
        for (int i = tid; i < c; i += TPB) {
            unsigned u = (unsigned)(cd[i] >> 32);
            if ((u & maskhi) == prefix) atomicAdd(&hist[(u >> shift) & 255], 1u);
        }
        __syncthreads();
        binselect256(hist, scanbuf, remaining, &s_sel, &s_run);
        remaining -= (int)s_run;
        prefix |= s_sel << shift;
        __syncthreads();
    }
    unsigned k50 = prefix;
    int t = remaining;  // take t smallest-index elements among key==k50 ties

    __shared__ int s_tn;
    __shared__ unsigned tiebuf[TIECAP];
    if (tid == 0) s_tn = 0;
    __syncthreads();
    float local = 0.f;
    for (int i = tid; i < c; i += TPB) {
        unsigned long long v = cd[i];
        unsigned u = (unsigned)(v >> 32);
        unsigned j = (unsigned)(v & 0xFFFFFFFFu);
        if (u < k50) {
            local += g_XC[j].w;  // yf
        } else if (u == k50) {
            int p = atomicAdd(&s_tn, 1);
            if (p < TIECAP) tiebuf[p] = j;
        }
    }
    __syncthreads();
    int nt = min(s_tn, TIECAP);
    for (int i = tid; i < nt; i += TPB) {
        unsigned ji = tiebuf[i];
        int rank = 0;
        for (int k = 0; k < nt; k++) rank += (tiebuf[k] < ji);
        if (rank < t) local += g_XC[ji].w;
    }
    __shared__ float sv[TPB];
    sv[tid] = local;
    __syncthreads();
    for (int st = TPB / 2; st > 0; st >>= 1) {
        if (tid < st) sv[tid] += sv[tid + st];
        __syncthreads();
    }
    if (tid == 0) {
        float v = sv[0];  // + BIAS (= 0)
        float sgn = (v > 0.f) ? 1.f : ((v < 0.f) ? -1.f : 0.f);
        out[row * 11 + 10] = sgn * g_scale[row];
    }
}

// ---------------------------------------------------------------------------
extern "C" void kernel_launch(void* const* d_in, const int* in_sizes, int n_in,
                              void* d_out, int out_size) {
    const float* x    = (const float*)d_in[0];
    const float* W    = (const float*)d_in[1];
    const float* bias = (const float*)d_in[2];
    const float* X    = (const float*)d_in[3];
    const int*   Y    = (const int*)d_in[4];
    float* out = (float*)d_out;

    k_setup<<<PREP_BLOCKS + LOGITS_BLOCKS, TPB>>>(X, Y, x, W, bias, out);
    k_thresh2<<<BB / TROWS, TPB>>>();
    k_main<<<dim3(RGRP, JCH), TPB>>>();
    k_final<<<BB, TPB>>>(out);
}